// round 1
// baseline (speedup 1.0000x reference)
#include <cuda_runtime.h>
#include <math.h>

#define PI_F 3.14159265358979323846f

// ---------------- scratch arena (no allocations allowed) ----------------
#define OFF_D7   0
#define OFF_D14  100352
#define OFF_D28  501760
#define OFF_C1   2107392
#define OFF_H1   2207744
#define OFF_SK1  2308096
#define OFF_C2   2408448
#define OFF_H2   2609152
#define OFF_SK2  2809856
#define OFF_C3   3010560
#define OFF_H3   3411968
#define OFF_C4   3813376
#define OFF_H4   4616192
#define OFF_H5   5419008
#define ARENA_SZ 7024640

__device__ float g_arena[ARENA_SZ];

// ---------------- block reduce ----------------
__device__ __forceinline__ float block_reduce_sum(float v, float* sh) {
    __syncthreads();
    int lane = threadIdx.x & 31, wid = threadIdx.x >> 5;
    #pragma unroll
    for (int o = 16; o > 0; o >>= 1) v += __shfl_down_sync(0xffffffffu, v, o);
    if (lane == 0) sh[wid] = v;
    __syncthreads();
    float r = 0.f;
    if (threadIdx.x < (blockDim.x >> 5)) r = sh[threadIdx.x];
    if (wid == 0) {
        #pragma unroll
        for (int o = 16; o > 0; o >>= 1) r += __shfl_down_sync(0xffffffffu, r, o);
        if (lane == 0) sh[0] = r;
    }
    __syncthreads();
    return sh[0];
}

// ---------------- SIFT ----------------
// One block per patch. Patch (PS x PS) is the strided subimage
// x[b, 0, ki::STEP, kj::STEP]. Descriptor written flat: desc[(b*P+off)*128 + d].
template<int PS, int STEP, int NT>
__global__ void sift_kernel(const float* __restrict__ x, float* __restrict__ desc) {
    constexpr int P    = STEP * STEP;
    constexpr int NPIX = PS * PS;
    constexpr int BK   = 2 * (PS / 5);
    constexpr int S    = PS / 4;
    constexpr int PAD  = BK / 4;
    constexpr float HALF   = BK * 0.5f;
    constexpr float INV_H2 = 1.0f / (HALF * HALF);

    __shared__ float patch[NPIX];
    __shared__ float pooled[128];
    __shared__ float g1[PS];
    __shared__ float red[32];
    __shared__ float invs2_sh;

    const int tid = threadIdx.x;
    const int b   = blockIdx.x / P;
    const int off = blockIdx.x % P;
    const int ki  = off / STEP, kj = off % STEP;
    const float* xb = x + b * 224 * 224;

    for (int i = tid; i < NPIX; i += NT) {
        int yy = i / PS, xx = i % PS;
        patch[i] = xb[(yy * STEP + ki) * 224 + xx * STEP + kj];
    }
    if (tid < PS) {  // gaussian, sigma = PS/sqrt(2) -> 0.5/s^2 = 1/PS^2
        float d = tid - (PS - 1) * 0.5f;
        g1[tid] = expf(-(d * d) / (float)(PS * PS));
    }
    if (tid < 128) pooled[tid] = 0.f;
    __syncthreads();
    if (tid == 0) {
        float s = 0.f;
        #pragma unroll
        for (int i = 0; i < PS; i++) s += g1[i];
        invs2_sh = 1.0f / (s * s);
    }
    __syncthreads();
    const float invs2 = invs2_sh;

    for (int i = tid; i < NPIX; i += NT) {
        int yy = i / PS, xx = i % PS;
        float xl = patch[yy * PS + (xx > 0      ? xx - 1 : 0)];
        float xr = patch[yy * PS + (xx < PS - 1 ? xx + 1 : PS - 1)];
        float yu = patch[(yy > 0      ? yy - 1 : 0)      * PS + xx];
        float yd = patch[(yy < PS - 1 ? yy + 1 : PS - 1) * PS + xx];
        float gx = 0.5f * (xr - xl);
        float gy = 0.5f * (yd - yu);
        float mag = sqrtf(gx * gx + gy * gy + 1e-10f) * g1[yy] * g1[xx] * invs2;
        float ori = atan2f(gy, gx + 1e-10f) + 2.0f * PI_F;
        float obig = ori * (4.0f / PI_F);           // 8 * ori / (2*pi)
        float b0f = floorf(obig);
        float w1  = obig - b0f;
        int bo0 = ((int)b0f) & 7;                   // b0f in [4,12], positive
        int bo1 = (bo0 + 1) & 7;
        float m0 = (1.f - w1) * mag, m1 = w1 * mag;
        #pragma unroll
        for (int oy = 0; oy < 4; oy++) {
            int ry = yy + PAD - oy * S;
            if (ry < 0 || ry >= BK) continue;
            float ty = HALF - fabsf(ry + 0.5f - HALF);
            #pragma unroll
            for (int ox = 0; ox < 4; ox++) {
                int rx = xx + PAD - ox * S;
                if (rx < 0 || rx >= BK) continue;
                float tx = HALF - fabsf(rx + 0.5f - HALF);
                float wgt = ty * tx * INV_H2;
                int base = oy * 4 + ox;
                atomicAdd(&pooled[bo0 * 16 + base], m0 * wgt);
                atomicAdd(&pooled[bo1 * 16 + base], m1 * wgt);
            }
        }
    }
    __syncthreads();
    float v  = (tid < 128) ? pooled[tid] : 0.f;
    float n1 = sqrtf(block_reduce_sum(v * v, red));
    float d1 = v / fmaxf(n1, 1e-12f);
    d1 = fminf(fmaxf(d1, 0.f), 0.2f);
    float n2 = sqrtf(block_reduce_sum(d1 * d1, red));
    float d2 = d1 / fmaxf(n2, 1e-12f);
    float s1 = block_reduce_sum(d2, red);           // all entries >= 0
    if (tid < 128)
        desc[(b * P + off) * 128 + tid] = sqrtf(d2 / fmaxf(s1, 1e-12f) + 1e-10f);
}

// ---------------- ConvTranspose2d (k=4, s=2, p=1), concat via 2 inputs ----------------
// out[n,co,oy,ox] = bias[co] + sum_{ky,kx valid} sum_ci in[ci, (oy+1-ky)/2, (ox+1-kx)/2] * w[ci,co,ky,kx]
__global__ void convt_kernel(const float* __restrict__ in1, int C1,
                             const float* __restrict__ in2, int C2,
                             const float* __restrict__ w, const float* __restrict__ bias,
                             float* __restrict__ out,
                             int Cout, int Hin, int Win, int total) {
    int idx = blockIdx.x * blockDim.x + threadIdx.x;
    if (idx >= total) return;
    const int Hout = Hin * 2, Wout = Win * 2;
    int ox = idx % Wout;
    int oy = (idx / Wout) % Hout;
    int co = (idx / (Wout * Hout)) % Cout;
    int n  = idx / (Wout * Hout * Cout);

    float acc = bias[co];
    #pragma unroll
    for (int ky = 0; ky < 4; ky++) {
        int ty = oy + 1 - ky;
        if (ty < 0 || (ty & 1)) continue;
        int iy = ty >> 1;
        if (iy >= Hin) continue;
        #pragma unroll
        for (int kx = 0; kx < 4; kx++) {
            int tx = ox + 1 - kx;
            if (tx < 0 || (tx & 1)) continue;
            int ix = tx >> 1;
            if (ix >= Win) continue;
            int spat = iy * Win + ix;
            int wk = ky * 4 + kx;
            for (int ci = 0; ci < C1; ci++)
                acc += in1[(n * C1 + ci) * Hin * Win + spat] * w[(ci * Cout + co) * 16 + wk];
            for (int ci = 0; ci < C2; ci++)
                acc += in2[(n * C2 + ci) * Hin * Win + spat] * w[((C1 + ci) * Cout + co) * 16 + wk];
        }
    }
    out[idx] = acc;
}

// ---------------- GroupNorm + ReLU ----------------
__global__ void gn_relu_kernel(const float* __restrict__ in, float* __restrict__ out,
                               const float* __restrict__ gamma, const float* __restrict__ beta,
                               int C, int HW, int groups) {
    __shared__ float red[32];
    int n = blockIdx.x / groups, g = blockIdx.x % groups;
    int cpg = C / groups;
    int cnt = cpg * HW;
    const float* p = in  + (size_t)(n * C + g * cpg) * HW;
    float*       q = out + (size_t)(n * C + g * cpg) * HW;
    float s = 0.f, ss = 0.f;
    for (int i = threadIdx.x; i < cnt; i += blockDim.x) {
        float v = p[i]; s += v; ss += v * v;
    }
    float sum  = block_reduce_sum(s, red);
    float sum2 = block_reduce_sum(ss, red);
    float mean = sum / cnt;
    float var  = sum2 / cnt - mean * mean;
    float inv  = rsqrtf(var + 1e-5f);
    for (int i = threadIdx.x; i < cnt; i += blockDim.x) {
        int c = g * cpg + i / HW;
        float v = (p[i] - mean) * inv * gamma[c] + beta[c];
        q[i] = fmaxf(v, 0.f);
    }
}

// ---------------- 1x1 skip conv (Cin=128) ----------------
__global__ void skip_kernel(const float* __restrict__ in, const float* __restrict__ w,
                            const float* __restrict__ b, float* __restrict__ out,
                            int Cout, int HW, int total) {
    int idx = blockIdx.x * blockDim.x + threadIdx.x;
    if (idx >= total) return;
    int s = idx % HW;
    int o = (idx / HW) % Cout;
    int n = idx / (HW * Cout);
    float acc = b[o];
    const float* ip = in + (size_t)n * 128 * HW + s;
    const float* wp = w + o * 128;
    #pragma unroll 8
    for (int c = 0; c < 128; c++) acc += ip[c * HW] * wp[c];
    out[idx] = acc;
}

// ---------------- joint bilateral blur (5x5, reflect) + tanh*scale ----------------
__global__ void jbf_tanh_kernel(const float* __restrict__ h, const float* __restrict__ x,
                                float* __restrict__ out, int total) {
    const int H = 224, W = 224;
    int idx = blockIdx.x * blockDim.x + threadIdx.x;
    if (idx >= total) return;
    int xx = idx % W;
    int y  = (idx / W) % H;
    int b  = idx / (W * H);
    const float* g  = x + (size_t)b * H * W;
    const float* h0 = h + (size_t)(b * 2 + 0) * H * W;
    const float* h1 = h + (size_t)(b * 2 + 1) * H * W;
    float gc = g[y * W + xx];

    float gs[5]; float ssum = 0.f;
    #pragma unroll
    for (int i = 0; i < 5; i++) { float d = (float)(i - 2); gs[i] = expf(-0.5f * d * d / 2.25f); ssum += gs[i]; }
    #pragma unroll
    for (int i = 0; i < 5; i++) gs[i] /= ssum;

    float wsum = 0.f, a0 = 0.f, a1 = 0.f;
    #pragma unroll
    for (int dy = -2; dy <= 2; dy++) {
        int yy = y + dy;
        yy = yy < 0 ? -yy : (yy >= H ? 2 * H - 2 - yy : yy);
        #pragma unroll
        for (int dx = -2; dx <= 2; dx++) {
            int x2 = xx + dx;
            x2 = x2 < 0 ? -x2 : (x2 >= W ? 2 * W - 2 - x2 : x2);
            float d = g[yy * W + x2] - gc;
            // guide has 2 identical channels: cd2 = (2|d|)^2 = 4 d^2; exp(-0.5/0.01 * cd2)
            float k = gs[dy + 2] * gs[dx + 2] * expf(-200.f * d * d);
            wsum += k;
            a0 += k * h0[yy * W + x2];
            a1 += k * h1[yy * W + x2];
        }
    }
    float inv = 1.f / wsum;
    out[(size_t)(b * 2 + 0) * H * W + y * W + xx] = tanhf(a0 * inv) * 0.436f;
    out[(size_t)(b * 2 + 1) * H * W + y * W + xx] = tanhf(a1 * inv) * 0.615f;
}

// ---------------- launch ----------------
extern "C" void kernel_launch(void* const* d_in, const int* in_sizes, int n_in,
                              void* d_out, int out_size) {
    const float* x   = (const float*)d_in[0];
    const float* d1w = (const float*)d_in[1];  const float* d1b = (const float*)d_in[2];
    const float* g1w = (const float*)d_in[3];  const float* g1b = (const float*)d_in[4];
    const float* s1w = (const float*)d_in[5];  const float* s1b = (const float*)d_in[6];
    const float* d2w = (const float*)d_in[7];  const float* d2b = (const float*)d_in[8];
    const float* g2w = (const float*)d_in[9];  const float* g2b = (const float*)d_in[10];
    const float* s2w = (const float*)d_in[11]; const float* s2b = (const float*)d_in[12];
    const float* d3w = (const float*)d_in[13]; const float* d3b = (const float*)d_in[14];
    const float* g3w = (const float*)d_in[15]; const float* g3b = (const float*)d_in[16];
    const float* d4w = (const float*)d_in[17]; const float* d4b = (const float*)d_in[18];
    const float* g4w = (const float*)d_in[19]; const float* g4b = (const float*)d_in[20];
    const float* fw  = (const float*)d_in[21]; const float* fb  = (const float*)d_in[22];
    float* out = (float*)d_out;

    const int B = in_sizes[0] / (224 * 224);

    float* arena = nullptr;
    cudaGetSymbolAddress((void**)&arena, g_arena);
    float* D7  = arena + OFF_D7;
    float* D14 = arena + OFF_D14;
    float* D28 = arena + OFF_D28;
    float* C1b = arena + OFF_C1;
    float* H1  = arena + OFF_H1;
    float* SK1 = arena + OFF_SK1;
    float* C2b = arena + OFF_C2;
    float* H2  = arena + OFF_H2;
    float* SK2 = arena + OFF_SK2;
    float* C3b = arena + OFF_C3;
    float* H3  = arena + OFF_H3;
    float* C4b = arena + OFF_C4;
    float* H4  = arena + OFF_H4;
    float* H5  = arena + OFF_H5;

    // SIFT stages
    sift_kernel<32, 7, 256><<<B * 49,  256>>>(x, D7);
    sift_kernel<16, 14, 256><<<B * 196, 256>>>(x, D14);
    sift_kernel<8, 28, 128><<<B * 784, 128>>>(x, D28);

    // layer 1: convT(128->32, 7->14), GN(8), skip1
    {
        int total = B * 32 * 14 * 14;
        convt_kernel<<<(total + 255) / 256, 256>>>(D7, 128, nullptr, 0, d1w, d1b, C1b, 32, 7, 7, total);
        gn_relu_kernel<<<B * 8, 256>>>(C1b, H1, g1w, g1b, 32, 196, 8);
        skip_kernel<<<(total + 255) / 256, 256>>>(D14, s1w, s1b, SK1, 32, 196, total);
    }
    // layer 2: convT(cat(32,32)->16, 14->28), GN(4), skip2
    {
        int total = B * 16 * 28 * 28;
        convt_kernel<<<(total + 255) / 256, 256>>>(H1, 32, SK1, 32, d2w, d2b, C2b, 16, 14, 14, total);
        gn_relu_kernel<<<B * 4, 256>>>(C2b, H2, g2w, g2b, 16, 784, 4);
        skip_kernel<<<(total + 255) / 256, 256>>>(D28, s2w, s2b, SK2, 16, 784, total);
    }
    // layer 3: convT(cat(16,16)->8, 28->56), GN(2)
    {
        int total = B * 8 * 56 * 56;
        convt_kernel<<<(total + 255) / 256, 256>>>(H2, 16, SK2, 16, d3w, d3b, C3b, 8, 28, 28, total);
        gn_relu_kernel<<<B * 2, 256>>>(C3b, H3, g3w, g3b, 8, 3136, 2);
    }
    // layer 4: convT(8->4, 56->112), GN(1)
    {
        int total = B * 4 * 112 * 112;
        convt_kernel<<<(total + 255) / 256, 256>>>(H3, 8, nullptr, 0, d4w, d4b, C4b, 4, 56, 56, total);
        gn_relu_kernel<<<B * 1, 256>>>(C4b, H4, g4w, g4b, 4, 12544, 1);
    }
    // final: convT(4->2, 112->224)
    {
        int total = B * 2 * 224 * 224;
        convt_kernel<<<(total + 255) / 256, 256>>>(H4, 4, nullptr, 0, fw, fb, H5, 2, 112, 112, total);
    }
    // joint bilateral + tanh * scale
    {
        int total = B * 224 * 224;
        jbf_tanh_kernel<<<(total + 255) / 256, 256>>>(H5, x, out, total);
    }
}

// round 2
// speedup vs baseline: 1.6277x; 1.6277x over previous
#include <cuda_runtime.h>
#include <math.h>

#define PI_F 3.14159265358979323846f

// ---------------- scratch arena (no allocations allowed) ----------------
#define OFF_D7   0
#define OFF_D14  100352
#define OFF_D28  501760
#define OFF_C1   2107392
#define OFF_H1   2207744
#define OFF_SK1  2308096
#define OFF_C2   2408448
#define OFF_H2   2609152
#define OFF_SK2  2809856
#define OFF_C3   3010560
#define OFF_H3   3411968
#define OFF_C4   3813376
#define OFF_H4   4616192
#define OFF_H5   5419008
#define ARENA_SZ 7024640

__device__ float g_arena[ARENA_SZ];

// ---------------- block reduce ----------------
__device__ __forceinline__ float block_reduce_sum(float v, float* sh) {
    __syncthreads();
    int lane = threadIdx.x & 31, wid = threadIdx.x >> 5;
    #pragma unroll
    for (int o = 16; o > 0; o >>= 1) v += __shfl_down_sync(0xffffffffu, v, o);
    if (lane == 0) sh[wid] = v;
    __syncthreads();
    float r = 0.f;
    if (threadIdx.x < (blockDim.x >> 5)) r = sh[threadIdx.x];
    if (wid == 0) {
        #pragma unroll
        for (int o = 16; o > 0; o >>= 1) r += __shfl_down_sync(0xffffffffu, r, o);
        if (lane == 0) sh[0] = r;
    }
    __syncthreads();
    return sh[0];
}

// ---------------- SIFT ----------------
template<int PS, int STEP, int NT>
__global__ void sift_kernel(const float* __restrict__ x, float* __restrict__ desc) {
    constexpr int P    = STEP * STEP;
    constexpr int NPIX = PS * PS;
    constexpr int BK   = 2 * (PS / 5);
    constexpr int S    = PS / 4;
    constexpr int PAD  = BK / 4;
    constexpr float HALF   = BK * 0.5f;
    constexpr float INV_H2 = 1.0f / (HALF * HALF);

    __shared__ float patch[NPIX];
    __shared__ float pooled[128];
    __shared__ float g1[PS];
    __shared__ float red[32];
    __shared__ float invs2_sh;

    const int tid = threadIdx.x;
    const int b   = blockIdx.x / P;
    const int off = blockIdx.x % P;
    const int ki  = off / STEP, kj = off % STEP;
    const float* xb = x + b * 224 * 224;

    for (int i = tid; i < NPIX; i += NT) {
        int yy = i / PS, xx = i % PS;
        patch[i] = xb[(yy * STEP + ki) * 224 + xx * STEP + kj];
    }
    if (tid < PS) {
        float d = tid - (PS - 1) * 0.5f;
        g1[tid] = expf(-(d * d) / (float)(PS * PS));
    }
    if (tid < 128) pooled[tid] = 0.f;
    __syncthreads();
    if (tid == 0) {
        float s = 0.f;
        #pragma unroll
        for (int i = 0; i < PS; i++) s += g1[i];
        invs2_sh = 1.0f / (s * s);
    }
    __syncthreads();
    const float invs2 = invs2_sh;

    for (int i = tid; i < NPIX; i += NT) {
        int yy = i / PS, xx = i % PS;
        float xl = patch[yy * PS + (xx > 0      ? xx - 1 : 0)];
        float xr = patch[yy * PS + (xx < PS - 1 ? xx + 1 : PS - 1)];
        float yu = patch[(yy > 0      ? yy - 1 : 0)      * PS + xx];
        float yd = patch[(yy < PS - 1 ? yy + 1 : PS - 1) * PS + xx];
        float gx = 0.5f * (xr - xl);
        float gy = 0.5f * (yd - yu);
        float mag = sqrtf(gx * gx + gy * gy + 1e-10f) * g1[yy] * g1[xx] * invs2;
        float ori = atan2f(gy, gx + 1e-10f) + 2.0f * PI_F;
        float obig = ori * (4.0f / PI_F);
        float b0f = floorf(obig);
        float w1  = obig - b0f;
        int bo0 = ((int)b0f) & 7;
        int bo1 = (bo0 + 1) & 7;
        float m0 = (1.f - w1) * mag, m1 = w1 * mag;
        #pragma unroll
        for (int oy = 0; oy < 4; oy++) {
            int ry = yy + PAD - oy * S;
            if (ry < 0 || ry >= BK) continue;
            float ty = HALF - fabsf(ry + 0.5f - HALF);
            #pragma unroll
            for (int ox = 0; ox < 4; ox++) {
                int rx = xx + PAD - ox * S;
                if (rx < 0 || rx >= BK) continue;
                float tx = HALF - fabsf(rx + 0.5f - HALF);
                float wgt = ty * tx * INV_H2;
                int base = oy * 4 + ox;
                atomicAdd(&pooled[bo0 * 16 + base], m0 * wgt);
                atomicAdd(&pooled[bo1 * 16 + base], m1 * wgt);
            }
        }
    }
    __syncthreads();
    float v  = (tid < 128) ? pooled[tid] : 0.f;
    float n1 = sqrtf(block_reduce_sum(v * v, red));
    float d1 = v / fmaxf(n1, 1e-12f);
    d1 = fminf(fmaxf(d1, 0.f), 0.2f);
    float n2 = sqrtf(block_reduce_sum(d1 * d1, red));
    float d2 = d1 / fmaxf(n2, 1e-12f);
    float s1 = block_reduce_sum(d2, red);
    if (tid < 128)
        desc[(b * P + off) * 128 + tid] = sqrtf(d2 / fmaxf(s1, 1e-12f) + 1e-10f);
}

// ---------------- ConvTranspose2d (k=4,s=2,p=1), smem-tiled ----------------
// Each thread computes a vertical pair of 2x2 output quads for one co.
// Input (with zero halo) and this block's weight slice live in smem.
template<int CIN, int C1, int COUT, int COGRP, int HIN, int WIN, int TQ>
__global__ void convt_tile(const float* __restrict__ in1, const float* __restrict__ in2,
                           const float* __restrict__ w, const float* __restrict__ bias,
                           float* __restrict__ out) {
    constexpr int W2 = WIN + 2;
    constexpr int R  = TQ + 2;
    constexpr int PAIRS = (TQ + 1) / 2;
    constexpr int NT = COGRP * PAIRS * WIN;
    constexpr int IN_ELEMS = CIN * R * W2;
    constexpr int W_ELEMS  = COGRP * CIN * 16;

    extern __shared__ float sm[];
    float* s_in = sm;             // CIN x R x W2
    float* s_w  = sm + IN_ELEMS;  // COGRP x CIN x 16

    const int n   = blockIdx.z;
    const int cg  = blockIdx.y;
    const int qy_base = blockIdx.x * TQ;
    const int co0 = cg * COGRP;
    const int tid = threadIdx.x;

    for (int e = tid; e < W_ELEMS; e += NT) {
        int k  = e & 15;
        int ci = (e >> 4) % CIN;
        int cl = (e >> 4) / CIN;
        s_w[e] = w[(ci * COUT + co0 + cl) * 16 + k];
    }
    const int HW = HIN * WIN;
    for (int e = tid; e < IN_ELEMS; e += NT) {
        int c  = e % W2;
        int r  = (e / W2) % R;
        int ci = e / (W2 * R);
        int iy = qy_base - 1 + r;
        int ix = c - 1;
        float v = 0.f;
        if (iy >= 0 && iy < HIN && ix >= 0 && ix < WIN) {
            v = (ci < C1) ? in1[(n * C1 + ci) * HW + iy * WIN + ix]
                          : in2[(n * (CIN - C1) + (ci - C1)) * HW + iy * WIN + ix];
        }
        s_in[e] = v;
    }
    __syncthreads();

    const int qx = tid % WIN;
    const int pr = (tid / WIN) % PAIRS;
    const int cl = tid / (WIN * PAIRS);
    const int qyA = qy_base + pr * 2;
    const bool hasB = (pr * 2 + 1) < TQ;

    float aA00=0,aA01=0,aA10=0,aA11=0;
    float aB00=0,aB01=0,aB10=0,aB11=0;
    const float* wrow = s_w + cl * CIN * 16;
    const int ibase = (pr * 2) * W2 + qx;

    #pragma unroll 4
    for (int ci = 0; ci < CIN; ci++) {
        const float4* wp = (const float4*)(wrow + ci * 16);
        float4 w0 = wp[0], w1 = wp[1], w2 = wp[2], w3 = wp[3];
        const float* ip = s_in + ci * R * W2 + ibase;
        float i00=ip[0], i01=ip[1], i02=ip[2]; ip += W2;
        float i10=ip[0], i11=ip[1], i12=ip[2]; ip += W2;
        float i20=ip[0], i21=ip[1], i22=ip[2]; ip += W2;
        float i30=ip[0], i31=ip[1], i32=ip[2];
        // quad A (rows i0x,i1x,i2x)
        aA00 += i11*w1.y + i10*w1.w + i01*w3.y + i00*w3.w;
        aA01 += i12*w1.x + i11*w1.z + i02*w3.x + i01*w3.z;
        aA10 += i21*w0.y + i20*w0.w + i11*w2.y + i10*w2.w;
        aA11 += i22*w0.x + i21*w0.z + i12*w2.x + i11*w2.z;
        // quad B (rows i1x,i2x,i3x)
        aB00 += i21*w1.y + i20*w1.w + i11*w3.y + i10*w3.w;
        aB01 += i22*w1.x + i21*w1.z + i12*w3.x + i11*w3.z;
        aB10 += i31*w0.y + i30*w0.w + i21*w2.y + i20*w2.w;
        aB11 += i32*w0.x + i31*w0.z + i22*w2.x + i21*w2.z;
    }

    const float bb = bias[co0 + cl];
    const int WOUT = 2 * WIN, HOUT = 2 * HIN;
    float* op = out + (((size_t)n * COUT + co0 + cl) * HOUT + 2 * qyA) * WOUT + 2 * qx;
    op[0] = aA00 + bb; op[1] = aA01 + bb;
    op[WOUT] = aA10 + bb; op[WOUT + 1] = aA11 + bb;
    if (hasB) {
        op += 2 * WOUT;
        op[0] = aB00 + bb; op[1] = aB01 + bb;
        op[WOUT] = aB10 + bb; op[WOUT + 1] = aB11 + bb;
    }
}

// ---------------- GroupNorm + ReLU ----------------
__global__ void gn_relu_kernel(const float* __restrict__ in, float* __restrict__ out,
                               const float* __restrict__ gamma, const float* __restrict__ beta,
                               int C, int HW, int groups) {
    __shared__ float red[32];
    int n = blockIdx.x / groups, g = blockIdx.x % groups;
    int cpg = C / groups;
    int cnt = cpg * HW;
    const float* p = in  + (size_t)(n * C + g * cpg) * HW;
    float*       q = out + (size_t)(n * C + g * cpg) * HW;
    float s = 0.f, ss = 0.f;
    for (int i = threadIdx.x; i < cnt; i += blockDim.x) {
        float v = p[i]; s += v; ss += v * v;
    }
    float sum  = block_reduce_sum(s, red);
    float sum2 = block_reduce_sum(ss, red);
    float mean = sum / cnt;
    float var  = sum2 / cnt - mean * mean;
    float inv  = rsqrtf(var + 1e-5f);
    for (int i = threadIdx.x; i < cnt; i += blockDim.x) {
        int c = g * cpg + i / HW;
        float v = (p[i] - mean) * inv * gamma[c] + beta[c];
        q[i] = fmaxf(v, 0.f);
    }
}

// ---------------- 1x1 skip conv (Cin=128) ----------------
__global__ void skip_kernel(const float* __restrict__ in, const float* __restrict__ w,
                            const float* __restrict__ b, float* __restrict__ out,
                            int Cout, int HW, int total) {
    int idx = blockIdx.x * blockDim.x + threadIdx.x;
    if (idx >= total) return;
    int s = idx % HW;
    int o = (idx / HW) % Cout;
    int n = idx / (HW * Cout);
    float acc = b[o];
    const float* ip = in + (size_t)n * 128 * HW + s;
    const float* wp = w + o * 128;
    #pragma unroll 8
    for (int c = 0; c < 128; c++) acc += ip[c * HW] * wp[c];
    out[idx] = acc;
}

// ---------------- fast e^{-t} (t >= 0), FMA-only ----------------
__device__ __forceinline__ float exp_neg(float t) {
    float z = fmaxf(t * -1.44269504f, -126.f);
    float nf = floorf(z);
    float f = z - nf;
    float p = fmaf(f, 1.33335581e-3f, 9.61812910e-3f);
    p = fmaf(f, p, 5.55041087e-2f);
    p = fmaf(f, p, 2.40226507e-1f);
    p = fmaf(f, p, 6.93147181e-1f);
    p = fmaf(f, p, 1.0f);
    return p * __int_as_float(((int)nf + 127) << 23);
}

// ---------------- joint bilateral (5x5, reflect) + tanh*scale, smem-tiled ----------------
__global__ void jbf_tanh_kernel(const float* __restrict__ h, const float* __restrict__ x,
                                float* __restrict__ out) {
    const int H = 224, W = 224;
    const int TS = 16, HS = 20;             // tile, tile+halo
    __shared__ float sg[HS * HS], sh0[HS * HS], sh1[HS * HS];

    const int b  = blockIdx.z;
    const int by = blockIdx.y * TS, bx = blockIdx.x * TS;
    const int tid = threadIdx.x;
    const float* g  = x + (size_t)b * H * W;
    const float* h0 = h + (size_t)(b * 2 + 0) * H * W;
    const float* h1 = h + (size_t)(b * 2 + 1) * H * W;

    for (int e = tid; e < HS * HS; e += 256) {
        int r = e / HS, c = e % HS;
        int gy = by - 2 + r, gx = bx - 2 + c;
        gy = gy < 0 ? -gy : (gy >= H ? 2 * H - 2 - gy : gy);
        gx = gx < 0 ? -gx : (gx >= W ? 2 * W - 2 - gx : gx);
        int gi = gy * W + gx;
        sg[e] = g[gi]; sh0[e] = h0[gi]; sh1[e] = h1[gi];
    }
    __syncthreads();

    const int ly = tid / TS, lx = tid % TS;
    const int ci = (ly + 2) * HS + (lx + 2);
    const float gc = sg[ci];
    // raw (unnormalized) spatial gaussian; normalization cancels in wsum
    const float gs[5] = {0.41111229f, 0.80073740f, 1.0f, 0.80073740f, 0.41111229f};

    float wsum = 0.f, a0 = 0.f, a1 = 0.f;
    #pragma unroll
    for (int dy = 0; dy < 5; dy++) {
        #pragma unroll
        for (int dx = 0; dx < 5; dx++) {
            int si = (ly + dy) * HS + (lx + dx);
            float d = sg[si] - gc;
            float k = gs[dy] * gs[dx] * exp_neg(200.f * d * d);
            wsum += k;
            a0 += k * sh0[si];
            a1 += k * sh1[si];
        }
    }
    float inv = 1.f / wsum;
    int oi = (by + ly) * W + (bx + lx);
    out[(size_t)(b * 2 + 0) * H * W + oi] = tanhf(a0 * inv) * 0.436f;
    out[(size_t)(b * 2 + 1) * H * W + oi] = tanhf(a1 * inv) * 0.615f;
}

// ---------------- launch ----------------
extern "C" void kernel_launch(void* const* d_in, const int* in_sizes, int n_in,
                              void* d_out, int out_size) {
    const float* x   = (const float*)d_in[0];
    const float* d1w = (const float*)d_in[1];  const float* d1b = (const float*)d_in[2];
    const float* g1w = (const float*)d_in[3];  const float* g1b = (const float*)d_in[4];
    const float* s1w = (const float*)d_in[5];  const float* s1b = (const float*)d_in[6];
    const float* d2w = (const float*)d_in[7];  const float* d2b = (const float*)d_in[8];
    const float* g2w = (const float*)d_in[9];  const float* g2b = (const float*)d_in[10];
    const float* s2w = (const float*)d_in[11]; const float* s2b = (const float*)d_in[12];
    const float* d3w = (const float*)d_in[13]; const float* d3b = (const float*)d_in[14];
    const float* g3w = (const float*)d_in[15]; const float* g3b = (const float*)d_in[16];
    const float* d4w = (const float*)d_in[17]; const float* d4b = (const float*)d_in[18];
    const float* g4w = (const float*)d_in[19]; const float* g4b = (const float*)d_in[20];
    const float* fw  = (const float*)d_in[21]; const float* fb  = (const float*)d_in[22];
    float* out = (float*)d_out;

    const int B = in_sizes[0] / (224 * 224);

    float* arena = nullptr;
    cudaGetSymbolAddress((void**)&arena, g_arena);
    float* D7  = arena + OFF_D7;
    float* D14 = arena + OFF_D14;
    float* D28 = arena + OFF_D28;
    float* C1b = arena + OFF_C1;
    float* H1  = arena + OFF_H1;
    float* SK1 = arena + OFF_SK1;
    float* C2b = arena + OFF_C2;
    float* H2  = arena + OFF_H2;
    float* SK2 = arena + OFF_SK2;
    float* C3b = arena + OFF_C3;
    float* H3  = arena + OFF_H3;
    float* C4b = arena + OFF_C4;
    float* H4  = arena + OFF_H4;
    float* H5  = arena + OFF_H5;

    // SIFT stages
    sift_kernel<32, 7, 256><<<B * 49,  256>>>(x, D7);
    sift_kernel<16, 14, 256><<<B * 196, 256>>>(x, D14);
    sift_kernel<8, 28, 128><<<B * 784, 128>>>(x, D28);

    // ---- layer 1: convT(128->32, 7->14), GN(8), skip1 ----
    {
        constexpr int SM = (128*9*9 + 4*128*16) * 4;
        cudaFuncSetAttribute(convt_tile<128,128,32,4,7,7,7>,
                             cudaFuncAttributeMaxDynamicSharedMemorySize, SM);
        dim3 grid(1, 8, B);
        convt_tile<128,128,32,4,7,7,7><<<grid, 4*4*7, SM>>>(D7, D7, d1w, d1b, C1b);
        gn_relu_kernel<<<B * 8, 256>>>(C1b, H1, g1w, g1b, 32, 196, 8);
        int total = B * 32 * 196;
        skip_kernel<<<(total + 255) / 256, 256>>>(D14, s1w, s1b, SK1, 32, 196, total);
    }
    // ---- layer 2: convT(cat(32,32)->16, 14->28), GN(4), skip2 ----
    {
        constexpr int SM = (64*9*16 + 4*64*16) * 4;
        cudaFuncSetAttribute(convt_tile<64,32,16,4,14,14,7>,
                             cudaFuncAttributeMaxDynamicSharedMemorySize, SM);
        dim3 grid(2, 4, B);
        convt_tile<64,32,16,4,14,14,7><<<grid, 4*4*14, SM>>>(H1, SK1, d2w, d2b, C2b);
        gn_relu_kernel<<<B * 4, 256>>>(C2b, H2, g2w, g2b, 16, 784, 4);
        int total = B * 16 * 784;
        skip_kernel<<<(total + 255) / 256, 256>>>(D28, s2w, s2b, SK2, 16, 784, total);
    }
    // ---- layer 3: convT(cat(16,16)->8, 28->56), GN(2) ----
    {
        constexpr int SM = (32*16*30 + 2*32*16) * 4;
        cudaFuncSetAttribute(convt_tile<32,16,8,2,28,28,14>,
                             cudaFuncAttributeMaxDynamicSharedMemorySize, SM);
        dim3 grid(2, 4, B);
        convt_tile<32,16,8,2,28,28,14><<<grid, 2*7*28, SM>>>(H2, SK2, d3w, d3b, C3b);
        gn_relu_kernel<<<B * 2, 256>>>(C3b, H3, g3w, g3b, 8, 3136, 2);
    }
    // ---- layer 4: convT(8->4, 56->112), GN(1) ----
    {
        constexpr int SM = (8*16*58 + 1*8*16) * 4;
        cudaFuncSetAttribute(convt_tile<8,8,4,1,56,56,14>,
                             cudaFuncAttributeMaxDynamicSharedMemorySize, SM);
        dim3 grid(4, 4, B);
        convt_tile<8,8,4,1,56,56,14><<<grid, 1*7*56, SM>>>(H3, H3, d4w, d4b, C4b);
        gn_relu_kernel<<<B * 1, 256>>>(C4b, H4, g4w, g4b, 4, 12544, 1);
    }
    // ---- final: convT(4->2, 112->224) ----
    {
        constexpr int SM = (4*16*114 + 1*4*16) * 4;
        cudaFuncSetAttribute(convt_tile<4,4,2,1,112,112,14>,
                             cudaFuncAttributeMaxDynamicSharedMemorySize, SM);
        dim3 grid(8, 2, B);
        convt_tile<4,4,2,1,112,112,14><<<grid, 1*7*112, SM>>>(H4, H4, fw, fb, H5);
    }
    // ---- joint bilateral + tanh * scale ----
    {
        dim3 grid(14, 14, B);
        jbf_tanh_kernel<<<grid, 256>>>(H5, x, out);
    }
}

// round 3
// speedup vs baseline: 2.0951x; 1.2872x over previous
#include <cuda_runtime.h>
#include <math.h>

#define PI_F 3.14159265358979323846f

// ---------------- scratch arena ----------------
#define OFF_D7    0
#define OFF_D14   100352
#define OFF_D28   501760
#define OFF_C1    2107392
#define OFF_SK1   2308096
#define OFF_C2    2408448
#define OFF_SK2   2809856
#define OFF_C3    3010560
#define OFF_C4    3813376
#define OFF_H5    5419008
#define OFF_STATS 7024640
#define ARENA_SZ  7025664

__device__ float g_arena[ARENA_SZ];

// ---------------- block reduce ----------------
__device__ __forceinline__ float block_reduce_sum(float v, float* sh) {
    __syncthreads();
    int lane = threadIdx.x & 31, wid = threadIdx.x >> 5;
    #pragma unroll
    for (int o = 16; o > 0; o >>= 1) v += __shfl_down_sync(0xffffffffu, v, o);
    if (lane == 0) sh[wid] = v;
    __syncthreads();
    float r = 0.f;
    if (threadIdx.x < (blockDim.x >> 5)) r = sh[threadIdx.x];
    if (wid == 0) {
        #pragma unroll
        for (int o = 16; o > 0; o >>= 1) r += __shfl_down_sync(0xffffffffu, r, o);
        if (lane == 0) sh[0] = r;
    }
    __syncthreads();
    return sh[0];
}

// ---------------- SIFT body (one block per patch, 256 threads) ----------------
template<int PS, int STEP>
__device__ __forceinline__ void sift_body(const float* __restrict__ x, float* __restrict__ desc,
                                          int gbid, float* patch, float* pooled,
                                          float* g1, float* red) {
    constexpr int P    = STEP * STEP;
    constexpr int NPIX = PS * PS;
    constexpr int BK   = 2 * (PS / 5);
    constexpr int S    = PS / 4;
    constexpr int PAD  = BK / 4;
    constexpr float HALF   = BK * 0.5f;
    constexpr float INV_H2 = 1.0f / (HALF * HALF);
    constexpr int NT = 256;

    const int tid = threadIdx.x;
    const int b   = gbid / P;
    const int off = gbid % P;
    const int ki  = off / STEP, kj = off % STEP;
    const float* xb = x + b * 224 * 224;

    for (int i = tid; i < NPIX; i += NT) {
        int yy = i / PS, xx = i % PS;
        patch[i] = xb[(yy * STEP + ki) * 224 + xx * STEP + kj];
    }
    if (tid < PS) {
        float d = tid - (PS - 1) * 0.5f;
        g1[tid] = expf(-(d * d) / (float)(PS * PS));
    }
    if (tid < 128) pooled[tid] = 0.f;
    __syncthreads();
    float gsum = 0.f;
    #pragma unroll
    for (int i = 0; i < PS; i++) gsum += g1[i];
    const float invs2 = 1.0f / (gsum * gsum);

    for (int i = tid; i < NPIX; i += NT) {
        int yy = i / PS, xx = i % PS;
        float xl = patch[yy * PS + (xx > 0      ? xx - 1 : 0)];
        float xr = patch[yy * PS + (xx < PS - 1 ? xx + 1 : PS - 1)];
        float yu = patch[(yy > 0      ? yy - 1 : 0)      * PS + xx];
        float yd = patch[(yy < PS - 1 ? yy + 1 : PS - 1) * PS + xx];
        float gx = 0.5f * (xr - xl);
        float gy = 0.5f * (yd - yu);
        float mag = sqrtf(gx * gx + gy * gy + 1e-10f) * g1[yy] * g1[xx] * invs2;
        float ori = atan2f(gy, gx + 1e-10f) + 2.0f * PI_F;
        float obig = ori * (4.0f / PI_F);
        float b0f = floorf(obig);
        float w1  = obig - b0f;
        int bo0 = ((int)b0f) & 7;
        int bo1 = (bo0 + 1) & 7;
        float m0 = (1.f - w1) * mag, m1 = w1 * mag;
        #pragma unroll
        for (int oy = 0; oy < 4; oy++) {
            int ry = yy + PAD - oy * S;
            if (ry < 0 || ry >= BK) continue;
            float ty = HALF - fabsf(ry + 0.5f - HALF);
            #pragma unroll
            for (int ox = 0; ox < 4; ox++) {
                int rx = xx + PAD - ox * S;
                if (rx < 0 || rx >= BK) continue;
                float tx = HALF - fabsf(rx + 0.5f - HALF);
                float wgt = ty * tx * INV_H2;
                int base = oy * 4 + ox;
                atomicAdd(&pooled[bo0 * 16 + base], m0 * wgt);
                atomicAdd(&pooled[bo1 * 16 + base], m1 * wgt);
            }
        }
    }
    __syncthreads();
    float v  = (tid < 128) ? pooled[tid] : 0.f;
    float n1 = sqrtf(block_reduce_sum(v * v, red));
    float d1 = v / fmaxf(n1, 1e-12f);
    d1 = fminf(fmaxf(d1, 0.f), 0.2f);
    float n2 = sqrtf(block_reduce_sum(d1 * d1, red));
    float d2 = d1 / fmaxf(n2, 1e-12f);
    float s1 = block_reduce_sum(d2, red);
    if (tid < 128)
        desc[(b * P + off) * 128 + tid] = sqrtf(d2 / fmaxf(s1, 1e-12f) + 1e-10f);
}

// fused: all three SIFT scales in one launch; block 0 also zeroes the stats buffer
__global__ void sift_all_kernel(const float* __restrict__ x, float* __restrict__ d7,
                                float* __restrict__ d14, float* __restrict__ d28,
                                float* __restrict__ stats, int B) {
    __shared__ float patch[1024], pooled[128], g1[32], red[32];
    const int bid = blockIdx.x;
    if (bid == 0) {
        for (int i = threadIdx.x; i < 512; i += 256) stats[i] = 0.f;
    }
    const int n1 = B * 49, n2 = B * 245;
    if (bid < n1)      sift_body<32, 7>(x, d7,  bid,      patch, pooled, g1, red);
    else if (bid < n2) sift_body<16, 14>(x, d14, bid - n1, patch, pooled, g1, red);
    else               sift_body<8, 28>(x, d28, bid - n2, patch, pooled, g1, red);
}

// ---------------- fused 1x1 skip convs (Cin=128) ----------------
__global__ void skip_both_kernel(const float* __restrict__ d14, const float* __restrict__ d28,
                                 const float* __restrict__ w1, const float* __restrict__ b1,
                                 const float* __restrict__ w2, const float* __restrict__ b2,
                                 float* __restrict__ sk1, float* __restrict__ sk2, int B) {
    const int t1 = B * 32 * 196;
    const int t2 = B * 16 * 784;
    int idx = blockIdx.x * blockDim.x + threadIdx.x;
    const float* in; const float* w; const float* bb; float* out;
    int Cout, HW;
    if (idx < t1) { in = d14; w = w1; bb = b1; out = sk1; Cout = 32; HW = 196; }
    else {
        idx -= t1;
        if (idx >= t2) return;
        in = d28; w = w2; bb = b2; out = sk2; Cout = 16; HW = 784;
    }
    int s = idx % HW;
    int o = (idx / HW) % Cout;
    int n = idx / (HW * Cout);
    float acc = bb[o];
    const float* ip = in + (size_t)n * 128 * HW + s;
    const float* wp = w + o * 128;
    #pragma unroll 8
    for (int c = 0; c < 128; c++) acc += ip[c * HW] * wp[c];
    out[idx] = acc;
}

// ---------------- ConvTranspose2d (k=4,s=2,p=1), smem-tiled ----------------
// - optional fused GroupNorm+ReLU on input channels [0,C1) (stats from stats_in)
// - optional per-(n,group) raw sum/sumsq stats of output (into stats_out, atomics)
// - in-block ci-split (CSPLIT) for higher thread count, smem tree-reduce
template<int CIN, int C1, int COUT, int COGRP, int HIN, int WIN, int TQ, int CSPLIT,
         bool GN_IN, bool DO_STATS, int GIN, int GOUT>
__global__ void __launch_bounds__(448)
convt_tile(const float* __restrict__ in1, const float* __restrict__ in2,
           const float* __restrict__ w, const float* __restrict__ bias,
           const float* __restrict__ gnw, const float* __restrict__ gnb,
           const float* __restrict__ stats_in, float* __restrict__ stats_out,
           float* __restrict__ out) {
    constexpr int W2 = WIN + 2;
    constexpr int R  = TQ + 2;
    constexpr int PAIRS = (TQ + 1) / 2;
    constexpr int BASE = COGRP * PAIRS * WIN;
    constexpr int NT = BASE * CSPLIT;
    constexpr int IN_ELEMS = CIN * R * W2;
    constexpr int W_ELEMS  = COGRP * CIN * 16;
    constexpr int CCH = CIN / CSPLIT;
    constexpr int RED_SZ = (CSPLIT > 1) ? NT * 8 : 0;
    constexpr int SC_SZ  = GN_IN ? C1 : 0;
    constexpr int CPG_I = GN_IN ? (C1 / GIN) : 1;
    constexpr float CNT_I = (float)(CPG_I * HIN * WIN);
    constexpr int CPG_O = COUT / GOUT;

    extern __shared__ float sm[];
    float* s_in    = sm;
    float* s_w     = s_in + IN_ELEMS;
    float* s_red   = s_w + W_ELEMS;
    float* s_scale = s_red + RED_SZ;
    float* s_shift = s_scale + SC_SZ;
    float* s_stat  = s_shift + SC_SZ;

    const int n   = blockIdx.z;
    const int cg  = blockIdx.y;
    const int qy_base = blockIdx.x * TQ;
    const int co0 = cg * COGRP;
    const int tid = threadIdx.x;

    if (DO_STATS && tid < 2 * COGRP) s_stat[tid] = 0.f;

    if (GN_IN) {
        for (int c = tid; c < C1; c += NT) {
            int g = c / CPG_I;
            float s  = stats_in[(n * GIN + g) * 2];
            float ss = stats_in[(n * GIN + g) * 2 + 1];
            float m = s / CNT_I;
            float var = ss / CNT_I - m * m;
            float inv = rsqrtf(var + 1e-5f);
            float sc = inv * gnw[c];
            s_scale[c] = sc;
            s_shift[c] = gnb[c] - m * sc;
        }
    }
    for (int e = tid; e < W_ELEMS; e += NT) {
        int k  = e & 15;
        int ci = (e >> 4) % CIN;
        int cl = (e >> 4) / CIN;
        s_w[e] = w[(ci * COUT + co0 + cl) * 16 + k];
    }
    __syncthreads();

    const int HW = HIN * WIN;
    for (int e = tid; e < IN_ELEMS; e += NT) {
        int c  = e % W2;
        int r  = (e / W2) % R;
        int ci = e / (W2 * R);
        int iy = qy_base - 1 + r;
        int ix = c - 1;
        float v = 0.f;
        if (iy >= 0 && iy < HIN && ix >= 0 && ix < WIN) {
            v = (ci < C1) ? in1[(n * C1 + ci) * HW + iy * WIN + ix]
                          : in2[(n * (CIN - C1) + (ci - C1)) * HW + iy * WIN + ix];
            if (GN_IN && ci < C1)
                v = fmaxf(fmaf(v, s_scale[ci], s_shift[ci]), 0.f);
        }
        s_in[e] = v;
    }
    __syncthreads();

    const int base_tid = tid % BASE;
    const int chunk    = tid / BASE;
    const int qx = base_tid % WIN;
    const int pr = (base_tid / WIN) % PAIRS;
    const int cl = base_tid / (WIN * PAIRS);
    const int qyA = qy_base + pr * 2;
    const bool hasB = (pr * 2 + 1) < TQ;

    float aA00=0,aA01=0,aA10=0,aA11=0;
    float aB00=0,aB01=0,aB10=0,aB11=0;
    const float* wrow = s_w + cl * CIN * 16;
    const int ibase = (pr * 2) * W2 + qx;

    #pragma unroll 4
    for (int ci = chunk * CCH; ci < (chunk + 1) * CCH; ci++) {
        const float4* wp = (const float4*)(wrow + ci * 16);
        float4 w0 = wp[0], w1 = wp[1], w2 = wp[2], w3 = wp[3];
        const float* ip = s_in + ci * R * W2 + ibase;
        float i00=ip[0], i01=ip[1], i02=ip[2]; ip += W2;
        float i10=ip[0], i11=ip[1], i12=ip[2]; ip += W2;
        float i20=ip[0], i21=ip[1], i22=ip[2]; ip += W2;
        float i30=0.f, i31=0.f, i32=0.f;
        if (hasB) { i30=ip[0]; i31=ip[1]; i32=ip[2]; }
        aA00 += i11*w1.y + i10*w1.w + i01*w3.y + i00*w3.w;
        aA01 += i12*w1.x + i11*w1.z + i02*w3.x + i01*w3.z;
        aA10 += i21*w0.y + i20*w0.w + i11*w2.y + i10*w2.w;
        aA11 += i22*w0.x + i21*w0.z + i12*w2.x + i11*w2.z;
        aB00 += i21*w1.y + i20*w1.w + i11*w3.y + i10*w3.w;
        aB01 += i22*w1.x + i21*w1.z + i12*w3.x + i11*w3.z;
        aB10 += i31*w0.y + i30*w0.w + i21*w2.y + i20*w2.w;
        aB11 += i32*w0.x + i31*w0.z + i22*w2.x + i21*w2.z;
    }

    if (CSPLIT > 1) {
        float* my = s_red + tid * 8;
        my[0]=aA00; my[1]=aA01; my[2]=aA10; my[3]=aA11;
        my[4]=aB00; my[5]=aB01; my[6]=aB10; my[7]=aB11;
        __syncthreads();
        if (chunk == 0) {
            #pragma unroll
            for (int c = 1; c < CSPLIT; c++) {
                const float* o = s_red + (c * BASE + base_tid) * 8;
                aA00+=o[0]; aA01+=o[1]; aA10+=o[2]; aA11+=o[3];
                aB00+=o[4]; aB01+=o[5]; aB10+=o[6]; aB11+=o[7];
            }
        }
    }

    if (chunk == 0) {
        const float bb = bias[co0 + cl];
        const int WOUT = 2 * WIN, HOUT = 2 * HIN;
        float* op = out + (((size_t)n * COUT + co0 + cl) * HOUT + 2 * qyA) * WOUT + 2 * qx;
        float v0 = aA00 + bb, v1 = aA01 + bb, v2 = aA10 + bb, v3 = aA11 + bb;
        op[0] = v0; op[1] = v1; op[WOUT] = v2; op[WOUT + 1] = v3;
        float s  = v0 + v1 + v2 + v3;
        float ss = v0*v0 + v1*v1 + v2*v2 + v3*v3;
        if (hasB) {
            op += 2 * WOUT;
            float u0 = aB00 + bb, u1 = aB01 + bb, u2 = aB10 + bb, u3 = aB11 + bb;
            op[0] = u0; op[1] = u1; op[WOUT] = u2; op[WOUT + 1] = u3;
            s  += u0 + u1 + u2 + u3;
            ss += u0*u0 + u1*u1 + u2*u2 + u3*u3;
        }
        if (DO_STATS) {
            atomicAdd(&s_stat[cl * 2],     s);
            atomicAdd(&s_stat[cl * 2 + 1], ss);
        }
    }
    if (DO_STATS) {
        __syncthreads();
        if (tid < COGRP) {
            int g = (co0 + tid) / CPG_O;
            atomicAdd(&stats_out[(n * GOUT + g) * 2],     s_stat[tid * 2]);
            atomicAdd(&stats_out[(n * GOUT + g) * 2 + 1], s_stat[tid * 2 + 1]);
        }
    }
}

// ---------------- fast e^{-t} (t >= 0), FMA-only ----------------
__device__ __forceinline__ float exp_neg(float t) {
    float z = fmaxf(t * -1.44269504f, -126.f);
    float nf = floorf(z);
    float f = z - nf;
    float p = fmaf(f, 1.33335581e-3f, 9.61812910e-3f);
    p = fmaf(f, p, 5.55041087e-2f);
    p = fmaf(f, p, 2.40226507e-1f);
    p = fmaf(f, p, 6.93147181e-1f);
    p = fmaf(f, p, 1.0f);
    return p * __int_as_float(((int)nf + 127) << 23);
}

// ---------------- joint bilateral (5x5, reflect) + tanh*scale ----------------
__global__ void jbf_tanh_kernel(const float* __restrict__ h, const float* __restrict__ x,
                                float* __restrict__ out) {
    const int H = 224, W = 224;
    const int TS = 16, HS = 20;
    __shared__ float sg[HS * HS], sh0[HS * HS], sh1[HS * HS];

    const int b  = blockIdx.z;
    const int by = blockIdx.y * TS, bx = blockIdx.x * TS;
    const int tid = threadIdx.x;
    const float* g  = x + (size_t)b * H * W;
    const float* h0 = h + (size_t)(b * 2 + 0) * H * W;
    const float* h1 = h + (size_t)(b * 2 + 1) * H * W;

    for (int e = tid; e < HS * HS; e += 256) {
        int r = e / HS, c = e % HS;
        int gy = by - 2 + r, gx = bx - 2 + c;
        gy = gy < 0 ? -gy : (gy >= H ? 2 * H - 2 - gy : gy);
        gx = gx < 0 ? -gx : (gx >= W ? 2 * W - 2 - gx : gx);
        int gi = gy * W + gx;
        sg[e] = g[gi]; sh0[e] = h0[gi]; sh1[e] = h1[gi];
    }
    __syncthreads();

    const int ly = tid / TS, lx = tid % TS;
    const int ci = (ly + 2) * HS + (lx + 2);
    const float gc = sg[ci];
    const float gs[5] = {0.41111229f, 0.80073740f, 1.0f, 0.80073740f, 0.41111229f};

    float wsum = 0.f, a0 = 0.f, a1 = 0.f;
    #pragma unroll
    for (int dy = 0; dy < 5; dy++) {
        #pragma unroll
        for (int dx = 0; dx < 5; dx++) {
            int si = (ly + dy) * HS + (lx + dx);
            float d = sg[si] - gc;
            float k = gs[dy] * gs[dx] * exp_neg(200.f * d * d);
            wsum += k;
            a0 += k * sh0[si];
            a1 += k * sh1[si];
        }
    }
    float inv = 1.f / wsum;
    int oi = (by + ly) * W + (bx + lx);
    out[(size_t)(b * 2 + 0) * H * W + oi] = tanhf(a0 * inv) * 0.436f;
    out[(size_t)(b * 2 + 1) * H * W + oi] = tanhf(a1 * inv) * 0.615f;
}

// ---------------- launch ----------------
extern "C" void kernel_launch(void* const* d_in, const int* in_sizes, int n_in,
                              void* d_out, int out_size) {
    const float* x   = (const float*)d_in[0];
    const float* d1w = (const float*)d_in[1];  const float* d1b = (const float*)d_in[2];
    const float* g1w = (const float*)d_in[3];  const float* g1b = (const float*)d_in[4];
    const float* s1w = (const float*)d_in[5];  const float* s1b = (const float*)d_in[6];
    const float* d2w = (const float*)d_in[7];  const float* d2b = (const float*)d_in[8];
    const float* g2w = (const float*)d_in[9];  const float* g2b = (const float*)d_in[10];
    const float* s2w = (const float*)d_in[11]; const float* s2b = (const float*)d_in[12];
    const float* d3w = (const float*)d_in[13]; const float* d3b = (const float*)d_in[14];
    const float* g3w = (const float*)d_in[15]; const float* g3b = (const float*)d_in[16];
    const float* d4w = (const float*)d_in[17]; const float* d4b = (const float*)d_in[18];
    const float* g4w = (const float*)d_in[19]; const float* g4b = (const float*)d_in[20];
    const float* fw  = (const float*)d_in[21]; const float* fb  = (const float*)d_in[22];
    float* out = (float*)d_out;

    const int B = in_sizes[0] / (224 * 224);

    float* arena = nullptr;
    cudaGetSymbolAddress((void**)&arena, g_arena);
    float* D7  = arena + OFF_D7;
    float* D14 = arena + OFF_D14;
    float* D28 = arena + OFF_D28;
    float* C1b = arena + OFF_C1;
    float* SK1 = arena + OFF_SK1;
    float* C2b = arena + OFF_C2;
    float* SK2 = arena + OFF_SK2;
    float* C3b = arena + OFF_C3;
    float* C4b = arena + OFF_C4;
    float* H5  = arena + OFF_H5;
    float* ST  = arena + OFF_STATS;
    float* ST1 = ST;        // B*8*2
    float* ST2 = ST + 256;  // B*4*2
    float* ST3 = ST + 384;  // B*2*2
    float* ST4 = ST + 448;  // B*1*2

    // 1) fused SIFT (all scales) + stats zeroing
    sift_all_kernel<<<B * 1029, 256>>>(x, D7, D14, D28, ST, B);

    // 2) fused skip convs
    {
        int tot = B * (32 * 196 + 16 * 784);
        skip_both_kernel<<<(tot + 255) / 256, 256>>>(D14, D28, s1w, s1b, s2w, s2b, SK1, SK2, B);
    }

    // 3) convT1: 128->32, 7->14, stats out (G=8)
    {
        constexpr int SM = (128*9*9 + 2*128*16 + 448*8 + 4) * 4;
        auto k = convt_tile<128,128,32,2,7,7,7,8,false,true,1,8>;
        cudaFuncSetAttribute(k, cudaFuncAttributeMaxDynamicSharedMemorySize, SM);
        k<<<dim3(1,16,B), 448, SM>>>(D7, D7, d1w, d1b, nullptr, nullptr, nullptr, ST1, C1b);
    }
    // 4) convT2: cat(GN8(C1b), SK1) 64->16, 14->28, stats out (G=4)
    {
        constexpr int SM = (64*9*16 + 2*64*16 + 448*8 + 2*32 + 4) * 4;
        auto k = convt_tile<64,32,16,2,14,14,7,4,true,true,8,4>;
        cudaFuncSetAttribute(k, cudaFuncAttributeMaxDynamicSharedMemorySize, SM);
        k<<<dim3(2,8,B), 448, SM>>>(C1b, SK1, d2w, d2b, g1w, g1b, ST1, ST2, C2b);
    }
    // 5) convT3: cat(GN4(C2b), SK2) 32->8, 28->56, stats out (G=2)
    {
        constexpr int SM = (32*9*30 + 2*32*16 + 448*8 + 2*16 + 4) * 4;
        auto k = convt_tile<32,16,8,2,28,28,7,2,true,true,4,2>;
        cudaFuncSetAttribute(k, cudaFuncAttributeMaxDynamicSharedMemorySize, SM);
        k<<<dim3(4,4,B), 448, SM>>>(C2b, SK2, d3w, d3b, g2w, g2b, ST2, ST3, C3b);
    }
    // 6) convT4: GN2(C3b) 8->4, 56->112, stats out (G=1)
    {
        constexpr int SM = (8*9*58 + 1*8*16 + 448*8 + 2*8 + 2) * 4;
        auto k = convt_tile<8,8,4,1,56,56,7,2,true,true,2,1>;
        cudaFuncSetAttribute(k, cudaFuncAttributeMaxDynamicSharedMemorySize, SM);
        k<<<dim3(8,4,B), 448, SM>>>(C3b, C3b, d4w, d4b, g3w, g3b, ST3, ST4, C4b);
    }
    // 7) convT5: GN1(C4b) 4->2, 112->224, no stats
    {
        constexpr int SM = (4*9*114 + 1*4*16 + 2*4) * 4;
        auto k = convt_tile<4,4,2,1,112,112,7,1,true,false,1,1>;
        cudaFuncSetAttribute(k, cudaFuncAttributeMaxDynamicSharedMemorySize, SM);
        k<<<dim3(16,2,B), 448, SM>>>(C4b, C4b, fw, fb, g4w, g4b, ST4, nullptr, H5);
    }
    // 8) joint bilateral + tanh*scale
    {
        dim3 grid(14, 14, B);
        jbf_tanh_kernel<<<grid, 256>>>(H5, x, out);
    }
}

// round 4
// speedup vs baseline: 2.1324x; 1.0178x over previous
#include <cuda_runtime.h>
#include <math.h>

#define PI_F 3.14159265358979323846f

// ---------------- scratch arena ----------------
#define OFF_D7    0
#define OFF_D14   100352
#define OFF_D28   501760
#define OFF_C1    2107392
#define OFF_SK1   2308096
#define OFF_C2    2408448
#define OFF_SK2   2809856
#define OFF_C3    3010560
#define OFF_C4    3813376
#define OFF_STATS 5419008
#define ARENA_SZ  5420032

__device__ float g_arena[ARENA_SZ];

// ---------------- reductions ----------------
__device__ __forceinline__ float warp_allreduce(float v) {
    #pragma unroll
    for (int o = 16; o > 0; o >>= 1) v += __shfl_xor_sync(0xffffffffu, v, o);
    return v;
}

__device__ __forceinline__ float block_reduce_sum(float v, float* sh) {
    __syncthreads();
    int lane = threadIdx.x & 31, wid = threadIdx.x >> 5;
    #pragma unroll
    for (int o = 16; o > 0; o >>= 1) v += __shfl_down_sync(0xffffffffu, v, o);
    if (lane == 0) sh[wid] = v;
    __syncthreads();
    float r = 0.f;
    if (threadIdx.x < (blockDim.x >> 5)) r = sh[threadIdx.x];
    if (wid == 0) {
        #pragma unroll
        for (int o = 16; o > 0; o >>= 1) r += __shfl_down_sync(0xffffffffu, r, o);
        if (lane == 0) sh[0] = r;
    }
    __syncthreads();
    return sh[0];
}

// ---------------- SIFT: block-per-patch (PS=32) ----------------
template<int PS, int STEP>
__device__ __forceinline__ void sift_body(const float* __restrict__ x, float* __restrict__ desc,
                                          int gbid, float* patch, float* pooled,
                                          float* g1, float* red) {
    constexpr int P    = STEP * STEP;
    constexpr int NPIX = PS * PS;
    constexpr int BK   = 2 * (PS / 5);
    constexpr int S    = PS / 4;
    constexpr int PAD  = BK / 4;
    constexpr float HALF   = BK * 0.5f;
    constexpr float INV_H2 = 1.0f / (HALF * HALF);
    constexpr int NT = 256;

    const int tid = threadIdx.x;
    const int b   = gbid / P;
    const int off = gbid % P;
    const int ki  = off / STEP, kj = off % STEP;
    const float* xb = x + b * 224 * 224;

    for (int i = tid; i < NPIX; i += NT) {
        int yy = i / PS, xx = i % PS;
        patch[i] = xb[(yy * STEP + ki) * 224 + xx * STEP + kj];
    }
    if (tid < PS) {
        float d = tid - (PS - 1) * 0.5f;
        g1[tid] = expf(-(d * d) / (float)(PS * PS));
    }
    if (tid < 128) pooled[tid] = 0.f;
    __syncthreads();
    float gsum = 0.f;
    #pragma unroll
    for (int i = 0; i < PS; i++) gsum += g1[i];
    const float invs2 = 1.0f / (gsum * gsum);

    for (int i = tid; i < NPIX; i += NT) {
        int yy = i / PS, xx = i % PS;
        float xl = patch[yy * PS + (xx > 0      ? xx - 1 : 0)];
        float xr = patch[yy * PS + (xx < PS - 1 ? xx + 1 : PS - 1)];
        float yu = patch[(yy > 0      ? yy - 1 : 0)      * PS + xx];
        float yd = patch[(yy < PS - 1 ? yy + 1 : PS - 1) * PS + xx];
        float gx = 0.5f * (xr - xl);
        float gy = 0.5f * (yd - yu);
        float mag = sqrtf(gx * gx + gy * gy + 1e-10f) * g1[yy] * g1[xx] * invs2;
        float ori = atan2f(gy, gx + 1e-10f) + 2.0f * PI_F;
        float obig = ori * (4.0f / PI_F);
        float b0f = floorf(obig);
        float w1  = obig - b0f;
        int bo0 = ((int)b0f) & 7;
        int bo1 = (bo0 + 1) & 7;
        float m0 = (1.f - w1) * mag, m1 = w1 * mag;
        #pragma unroll
        for (int oy = 0; oy < 4; oy++) {
            int ry = yy + PAD - oy * S;
            if (ry < 0 || ry >= BK) continue;
            float ty = HALF - fabsf(ry + 0.5f - HALF);
            #pragma unroll
            for (int ox = 0; ox < 4; ox++) {
                int rx = xx + PAD - ox * S;
                if (rx < 0 || rx >= BK) continue;
                float tx = HALF - fabsf(rx + 0.5f - HALF);
                float wgt = ty * tx * INV_H2;
                int base = oy * 4 + ox;
                atomicAdd(&pooled[bo0 * 16 + base], m0 * wgt);
                atomicAdd(&pooled[bo1 * 16 + base], m1 * wgt);
            }
        }
    }
    __syncthreads();
    float v  = (tid < 128) ? pooled[tid] : 0.f;
    float n1 = sqrtf(block_reduce_sum(v * v, red));
    float d1 = v / fmaxf(n1, 1e-12f);
    d1 = fminf(fmaxf(d1, 0.f), 0.2f);
    float n2 = sqrtf(block_reduce_sum(d1 * d1, red));
    float d2 = d1 / fmaxf(n2, 1e-12f);
    float s1 = block_reduce_sum(d2, red);
    if (tid < 128)
        desc[(b * P + off) * 128 + tid] = sqrtf(d2 / fmaxf(s1, 1e-12f) + 1e-10f);
}

// ---------------- SIFT: warp-per-patch (PS=8,16) ----------------
template<int PS, int STEP>
__device__ __forceinline__ void sift_warp_body(const float* __restrict__ x, float* __restrict__ desc,
                                               int pid, int npatch, float* wsm) {
    constexpr int P    = STEP * STEP;
    constexpr int NPIX = PS * PS;
    constexpr int PPL  = NPIX / 32;
    constexpr int BK   = 2 * (PS / 5);
    constexpr int S    = PS / 4;
    constexpr int PAD  = BK / 4;
    constexpr float HALF   = BK * 0.5f;
    constexpr float INV_H2 = 1.0f / (HALF * HALF);

    if (pid >= npatch) return;
    const int lane = threadIdx.x & 31;
    const int b   = pid / P;
    const int off = pid % P;
    const int ki  = off / STEP, kj = off % STEP;
    const float* xb = x + b * 224 * 224;

    float* patch  = wsm;
    float* pooled = wsm + NPIX;
    float* g1     = wsm + NPIX + 128;

    #pragma unroll
    for (int k = 0; k < PPL; k++) {
        int i = lane + k * 32;
        int yy = i / PS, xx = i % PS;
        patch[i] = xb[(yy * STEP + ki) * 224 + xx * STEP + kj];
    }
    if (lane < PS) {
        float d = lane - (PS - 1) * 0.5f;
        g1[lane] = expf(-(d * d) / (float)(PS * PS));
    }
    #pragma unroll
    for (int j = 0; j < 4; j++) pooled[lane + j * 32] = 0.f;
    __syncwarp();

    float gsum = 0.f;
    #pragma unroll
    for (int i = 0; i < PS; i++) gsum += g1[i];
    const float invs2 = 1.0f / (gsum * gsum);

    #pragma unroll
    for (int k = 0; k < PPL; k++) {
        int i = lane + k * 32;
        int yy = i / PS, xx = i % PS;
        float xl = patch[yy * PS + (xx > 0      ? xx - 1 : 0)];
        float xr = patch[yy * PS + (xx < PS - 1 ? xx + 1 : PS - 1)];
        float yu = patch[(yy > 0      ? yy - 1 : 0)      * PS + xx];
        float yd = patch[(yy < PS - 1 ? yy + 1 : PS - 1) * PS + xx];
        float gx = 0.5f * (xr - xl);
        float gy = 0.5f * (yd - yu);
        float mag = sqrtf(gx * gx + gy * gy + 1e-10f) * g1[yy] * g1[xx] * invs2;
        float ori = atan2f(gy, gx + 1e-10f) + 2.0f * PI_F;
        float obig = ori * (4.0f / PI_F);
        float b0f = floorf(obig);
        float w1  = obig - b0f;
        int bo0 = ((int)b0f) & 7;
        int bo1 = (bo0 + 1) & 7;
        float m0 = (1.f - w1) * mag, m1 = w1 * mag;
        #pragma unroll
        for (int oy = 0; oy < 4; oy++) {
            int ry = yy + PAD - oy * S;
            if (ry < 0 || ry >= BK) continue;
            float ty = HALF - fabsf(ry + 0.5f - HALF);
            #pragma unroll
            for (int ox = 0; ox < 4; ox++) {
                int rx = xx + PAD - ox * S;
                if (rx < 0 || rx >= BK) continue;
                float tx = HALF - fabsf(rx + 0.5f - HALF);
                float wgt = ty * tx * INV_H2;
                int base = oy * 4 + ox;
                atomicAdd(&pooled[bo0 * 16 + base], m0 * wgt);
                atomicAdd(&pooled[bo1 * 16 + base], m1 * wgt);
            }
        }
    }
    __syncwarp();

    float v[4];
    float p = 0.f;
    #pragma unroll
    for (int j = 0; j < 4; j++) { v[j] = pooled[lane + j * 32]; p += v[j] * v[j]; }
    float n1 = sqrtf(warp_allreduce(p));
    float inv1 = 1.f / fmaxf(n1, 1e-12f);
    p = 0.f;
    #pragma unroll
    for (int j = 0; j < 4; j++) {
        v[j] = fminf(fmaxf(v[j] * inv1, 0.f), 0.2f);
        p += v[j] * v[j];
    }
    float n2 = sqrtf(warp_allreduce(p));
    float inv2 = 1.f / fmaxf(n2, 1e-12f);
    p = 0.f;
    #pragma unroll
    for (int j = 0; j < 4; j++) { v[j] *= inv2; p += v[j]; }
    float s1 = warp_allreduce(p);
    float invs = 1.f / fmaxf(s1, 1e-12f);
    #pragma unroll
    for (int j = 0; j < 4; j++)
        desc[pid * 128 + lane + j * 32] = sqrtf(v[j] * invs + 1e-10f);
}

// fused: all three SIFT scales; block 0 zeroes stats
__global__ void sift_all_kernel(const float* __restrict__ x, float* __restrict__ d7,
                                float* __restrict__ d14, float* __restrict__ d28,
                                float* __restrict__ stats, int B) {
    __shared__ float sm[3200];
    const int bid = blockIdx.x;
    const int tid = threadIdx.x;
    if (bid == 0) {
        for (int i = tid; i < 512; i += 256) stats[i] = 0.f;
    }
    const int nA = B * 49;
    const int nB = nA + (B * 196 + 7) / 8;
    if (bid < nA) {
        sift_body<32, 7>(x, d7, bid, sm, sm + 1024, sm + 1152, sm + 1184);
    } else if (bid < nB) {
        int wid = tid >> 5;
        int pid = (bid - nA) * 8 + wid;
        sift_warp_body<16, 14>(x, d14, pid, B * 196, sm + wid * 400);
    } else {
        int wid = tid >> 5;
        int pid = (bid - nB) * 8 + wid;
        sift_warp_body<8, 28>(x, d28, pid, B * 784, sm + wid * 208);
    }
}

// ---------------- fused 1x1 skip convs (Cin=128) ----------------
__global__ void skip_both_kernel(const float* __restrict__ d14, const float* __restrict__ d28,
                                 const float* __restrict__ w1, const float* __restrict__ b1,
                                 const float* __restrict__ w2, const float* __restrict__ b2,
                                 float* __restrict__ sk1, float* __restrict__ sk2, int B) {
    const int t1 = B * 32 * 196;
    const int t2 = B * 16 * 784;
    int idx = blockIdx.x * blockDim.x + threadIdx.x;
    const float* in; const float* w; const float* bb; float* out;
    int Cout, HW;
    if (idx < t1) { in = d14; w = w1; bb = b1; out = sk1; Cout = 32; HW = 196; }
    else {
        idx -= t1;
        if (idx >= t2) return;
        in = d28; w = w2; bb = b2; out = sk2; Cout = 16; HW = 784;
    }
    int s = idx % HW;
    int o = (idx / HW) % Cout;
    int n = idx / (HW * Cout);
    float acc = bb[o];
    const float* ip = in + (size_t)n * 128 * HW + s;
    const float* wp = w + o * 128;
    #pragma unroll 8
    for (int c = 0; c < 128; c++) acc += ip[c * HW] * wp[c];
    out[idx] = acc;
}

// ---------------- ConvTranspose2d (k=4,s=2,p=1), smem-tiled ----------------
template<int CIN, int C1, int COUT, int COGRP, int HIN, int WIN, int TQ, int CSPLIT,
         bool GN_IN, bool DO_STATS, int GIN, int GOUT>
__global__ void __launch_bounds__(448)
convt_tile(const float* __restrict__ in1, const float* __restrict__ in2,
           const float* __restrict__ w, const float* __restrict__ bias,
           const float* __restrict__ gnw, const float* __restrict__ gnb,
           const float* __restrict__ stats_in, float* __restrict__ stats_out,
           float* __restrict__ out) {
    constexpr int W2 = WIN + 2;
    constexpr int R  = TQ + 2;
    constexpr int PAIRS = (TQ + 1) / 2;
    constexpr int BASE = COGRP * PAIRS * WIN;
    constexpr int NT = BASE * CSPLIT;
    constexpr int IN_ELEMS = CIN * R * W2;
    constexpr int W_ELEMS  = COGRP * CIN * 16;
    constexpr int CCH = CIN / CSPLIT;
    constexpr int RED_SZ = (CSPLIT > 1) ? NT * 8 : 0;
    constexpr int SC_SZ  = GN_IN ? C1 : 0;
    constexpr int CPG_I = GN_IN ? (C1 / GIN) : 1;
    constexpr float CNT_I = (float)(CPG_I * HIN * WIN);
    constexpr int CPG_O = COUT / GOUT;

    extern __shared__ float sm[];
    float* s_in    = sm;
    float* s_w     = s_in + IN_ELEMS;
    float* s_red   = s_w + W_ELEMS;
    float* s_scale = s_red + RED_SZ;
    float* s_shift = s_scale + SC_SZ;
    float* s_stat  = s_shift + SC_SZ;

    const int n   = blockIdx.z;
    const int cg  = blockIdx.y;
    const int qy_base = blockIdx.x * TQ;
    const int co0 = cg * COGRP;
    const int tid = threadIdx.x;

    if (DO_STATS && tid < 2 * COGRP) s_stat[tid] = 0.f;

    if (GN_IN) {
        for (int c = tid; c < C1; c += NT) {
            int g = c / CPG_I;
            float s  = stats_in[(n * GIN + g) * 2];
            float ss = stats_in[(n * GIN + g) * 2 + 1];
            float m = s / CNT_I;
            float var = ss / CNT_I - m * m;
            float inv = rsqrtf(var + 1e-5f);
            float sc = inv * gnw[c];
            s_scale[c] = sc;
            s_shift[c] = gnb[c] - m * sc;
        }
    }
    for (int e = tid; e < W_ELEMS; e += NT) {
        int k  = e & 15;
        int ci = (e >> 4) % CIN;
        int cl = (e >> 4) / CIN;
        s_w[e] = w[(ci * COUT + co0 + cl) * 16 + k];
    }
    __syncthreads();

    const int HW = HIN * WIN;
    for (int e = tid; e < IN_ELEMS; e += NT) {
        int c  = e % W2;
        int r  = (e / W2) % R;
        int ci = e / (W2 * R);
        int iy = qy_base - 1 + r;
        int ix = c - 1;
        float v = 0.f;
        if (iy >= 0 && iy < HIN && ix >= 0 && ix < WIN) {
            v = (ci < C1) ? in1[(n * C1 + ci) * HW + iy * WIN + ix]
                          : in2[(n * (CIN - C1) + (ci - C1)) * HW + iy * WIN + ix];
            if (GN_IN && ci < C1)
                v = fmaxf(fmaf(v, s_scale[ci], s_shift[ci]), 0.f);
        }
        s_in[e] = v;
    }
    __syncthreads();

    const int base_tid = tid % BASE;
    const int chunk    = tid / BASE;
    const int qx = base_tid % WIN;
    const int pr = (base_tid / WIN) % PAIRS;
    const int cl = base_tid / (WIN * PAIRS);
    const int qyA = qy_base + pr * 2;
    const bool hasB = (pr * 2 + 1) < TQ;

    float aA00=0,aA01=0,aA10=0,aA11=0;
    float aB00=0,aB01=0,aB10=0,aB11=0;
    const float* wrow = s_w + cl * CIN * 16;
    const int ibase = (pr * 2) * W2 + qx;

    #pragma unroll 4
    for (int ci = chunk * CCH; ci < (chunk + 1) * CCH; ci++) {
        const float4* wp = (const float4*)(wrow + ci * 16);
        float4 w0 = wp[0], w1 = wp[1], w2 = wp[2], w3 = wp[3];
        const float* ip = s_in + ci * R * W2 + ibase;
        float i00=ip[0], i01=ip[1], i02=ip[2]; ip += W2;
        float i10=ip[0], i11=ip[1], i12=ip[2]; ip += W2;
        float i20=ip[0], i21=ip[1], i22=ip[2]; ip += W2;
        float i30=0.f, i31=0.f, i32=0.f;
        if (hasB) { i30=ip[0]; i31=ip[1]; i32=ip[2]; }
        aA00 += i11*w1.y + i10*w1.w + i01*w3.y + i00*w3.w;
        aA01 += i12*w1.x + i11*w1.z + i02*w3.x + i01*w3.z;
        aA10 += i21*w0.y + i20*w0.w + i11*w2.y + i10*w2.w;
        aA11 += i22*w0.x + i21*w0.z + i12*w2.x + i11*w2.z;
        aB00 += i21*w1.y + i20*w1.w + i11*w3.y + i10*w3.w;
        aB01 += i22*w1.x + i21*w1.z + i12*w3.x + i11*w3.z;
        aB10 += i31*w0.y + i30*w0.w + i21*w2.y + i20*w2.w;
        aB11 += i32*w0.x + i31*w0.z + i22*w2.x + i21*w2.z;
    }

    if (CSPLIT > 1) {
        float* my = s_red + tid * 8;
        my[0]=aA00; my[1]=aA01; my[2]=aA10; my[3]=aA11;
        my[4]=aB00; my[5]=aB01; my[6]=aB10; my[7]=aB11;
        __syncthreads();
        if (chunk == 0) {
            #pragma unroll
            for (int c = 1; c < CSPLIT; c++) {
                const float* o = s_red + (c * BASE + base_tid) * 8;
                aA00+=o[0]; aA01+=o[1]; aA10+=o[2]; aA11+=o[3];
                aB00+=o[4]; aB01+=o[5]; aB10+=o[6]; aB11+=o[7];
            }
        }
    }

    if (chunk == 0) {
        const float bb = bias[co0 + cl];
        const int WOUT = 2 * WIN, HOUT = 2 * HIN;
        float* op = out + (((size_t)n * COUT + co0 + cl) * HOUT + 2 * qyA) * WOUT + 2 * qx;
        float v0 = aA00 + bb, v1 = aA01 + bb, v2 = aA10 + bb, v3 = aA11 + bb;
        op[0] = v0; op[1] = v1; op[WOUT] = v2; op[WOUT + 1] = v3;
        float s  = v0 + v1 + v2 + v3;
        float ss = v0*v0 + v1*v1 + v2*v2 + v3*v3;
        if (hasB) {
            op += 2 * WOUT;
            float u0 = aB00 + bb, u1 = aB01 + bb, u2 = aB10 + bb, u3 = aB11 + bb;
            op[0] = u0; op[1] = u1; op[WOUT] = u2; op[WOUT + 1] = u3;
            s  += u0 + u1 + u2 + u3;
            ss += u0*u0 + u1*u1 + u2*u2 + u3*u3;
        }
        if (DO_STATS) {
            atomicAdd(&s_stat[cl * 2],     s);
            atomicAdd(&s_stat[cl * 2 + 1], ss);
        }
    }
    if (DO_STATS) {
        __syncthreads();
        if (tid < COGRP) {
            int g = (co0 + tid) / CPG_O;
            atomicAdd(&stats_out[(n * GOUT + g) * 2],     s_stat[tid * 2]);
            atomicAdd(&stats_out[(n * GOUT + g) * 2 + 1], s_stat[tid * 2 + 1]);
        }
    }
}

// ---------------- fast e^{-t} (t >= 0), FMA-only ----------------
__device__ __forceinline__ float exp_neg(float t) {
    float z = fmaxf(t * -1.44269504f, -126.f);
    float nf = floorf(z);
    float f = z - nf;
    float p = fmaf(f, 1.33335581e-3f, 9.61812910e-3f);
    p = fmaf(f, p, 5.55041087e-2f);
    p = fmaf(f, p, 2.40226507e-1f);
    p = fmaf(f, p, 6.93147181e-1f);
    p = fmaf(f, p, 1.0f);
    return p * __int_as_float(((int)nf + 127) << 23);
}

__device__ __forceinline__ int reflect224(int i) {
    return i < 0 ? -i : (i >= 224 ? 446 - i : i);
}

// ---------------- fused: GN1 + convT(4->2, 112->224) + jbf + tanh*scale ----------------
__global__ void jbf_fused_kernel(const float* __restrict__ c4, const float* __restrict__ x,
                                 const float* __restrict__ fw, const float* __restrict__ fb,
                                 const float* __restrict__ g4w, const float* __restrict__ g4b,
                                 const float* __restrict__ st4, float* __restrict__ out) {
    const int H = 224, W = 224;
    __shared__ float s_in[4 * 12 * 12];
    __shared__ float s_h0[400], s_h1[400], sg[400];
    __shared__ float s_fw[128];

    const int b = blockIdx.z, tyb = blockIdx.y, txb = blockIdx.x;
    const int by = tyb * 16, bx = txb * 16;
    const int tid = threadIdx.x;

    if (tid < 128) s_fw[tid] = fw[tid];

    // GN(groups=1) params from raw stats
    float ssum = st4[b * 2], ssq = st4[b * 2 + 1];
    float m = ssum / 50176.f;
    float var = ssq / 50176.f - m * m;
    float inv = rsqrtf(var + 1e-5f);

    const int iy0 = 8 * tyb - 2, ix0 = 8 * txb - 2;
    const float* cb = c4 + (size_t)b * 4 * 112 * 112;
    for (int e = tid; e < 576; e += 256) {
        int ci = e / 144;
        int rr = (e % 144) / 12, cc = e % 12;
        int iy = iy0 + rr, ix = ix0 + cc;
        float v = 0.f;
        if (iy >= 0 && iy < 112 && ix >= 0 && ix < 112) {
            float sc = inv * g4w[ci];
            float sh = g4b[ci] - m * sc;
            v = fmaxf(fmaf(cb[(ci * 112 + iy) * 112 + ix], sc, sh), 0.f);
        }
        s_in[e] = v;
    }
    const float* gx_ = x + (size_t)b * H * W;
    for (int e = tid; e < 400; e += 256) {
        int r = e / 20, c = e % 20;
        sg[e] = gx_[reflect224(by - 2 + r) * W + reflect224(bx - 2 + c)];
    }
    __syncthreads();

    const float fb0 = fb[0], fb1 = fb[1];
    for (int e = tid; e < 400; e += 256) {
        int r = e / 20, c = e % 20;
        int oy = reflect224(by - 2 + r);
        int ox = reflect224(bx - 2 + c);
        float a0 = fb0, a1 = fb1;
        #pragma unroll
        for (int ky = 0; ky < 4; ky++) {
            int t = oy + 1 - ky;
            if (t < 0 || (t & 1)) continue;
            int iy = t >> 1;
            if (iy >= 112) continue;
            int il = iy - iy0;
            #pragma unroll
            for (int kx = 0; kx < 4; kx++) {
                int u = ox + 1 - kx;
                if (u < 0 || (u & 1)) continue;
                int ix = u >> 1;
                if (ix >= 112) continue;
                int jl = ix - ix0;
                int k = ky * 4 + kx;
                #pragma unroll
                for (int ci = 0; ci < 4; ci++) {
                    float v = s_in[ci * 144 + il * 12 + jl];
                    a0 = fmaf(v, s_fw[ci * 32 + k], a0);
                    a1 = fmaf(v, s_fw[ci * 32 + 16 + k], a1);
                }
            }
        }
        s_h0[e] = a0; s_h1[e] = a1;
    }
    __syncthreads();

    const int ly = tid / 16, lx = tid % 16;
    const int ci_ = (ly + 2) * 20 + (lx + 2);
    const float gc = sg[ci_];
    const float gs[5] = {0.41111229f, 0.80073740f, 1.0f, 0.80073740f, 0.41111229f};

    float wsum = 0.f, a0 = 0.f, a1 = 0.f;
    #pragma unroll
    for (int dy = 0; dy < 5; dy++) {
        #pragma unroll
        for (int dx = 0; dx < 5; dx++) {
            int si = (ly + dy) * 20 + (lx + dx);
            float d = sg[si] - gc;
            float k = gs[dy] * gs[dx] * exp_neg(200.f * d * d);
            wsum += k;
            a0 += k * s_h0[si];
            a1 += k * s_h1[si];
        }
    }
    float invw = 1.f / wsum;
    int oi = (by + ly) * W + (bx + lx);
    out[(size_t)(b * 2 + 0) * H * W + oi] = tanhf(a0 * invw) * 0.436f;
    out[(size_t)(b * 2 + 1) * H * W + oi] = tanhf(a1 * invw) * 0.615f;
}

// ---------------- launch ----------------
extern "C" void kernel_launch(void* const* d_in, const int* in_sizes, int n_in,
                              void* d_out, int out_size) {
    const float* x   = (const float*)d_in[0];
    const float* d1w = (const float*)d_in[1];  const float* d1b = (const float*)d_in[2];
    const float* g1w = (const float*)d_in[3];  const float* g1b = (const float*)d_in[4];
    const float* s1w = (const float*)d_in[5];  const float* s1b = (const float*)d_in[6];
    const float* d2w = (const float*)d_in[7];  const float* d2b = (const float*)d_in[8];
    const float* g2w = (const float*)d_in[9];  const float* g2b = (const float*)d_in[10];
    const float* s2w = (const float*)d_in[11]; const float* s2b = (const float*)d_in[12];
    const float* d3w = (const float*)d_in[13]; const float* d3b = (const float*)d_in[14];
    const float* g3w = (const float*)d_in[15]; const float* g3b = (const float*)d_in[16];
    const float* d4w = (const float*)d_in[17]; const float* d4b = (const float*)d_in[18];
    const float* g4w = (const float*)d_in[19]; const float* g4b = (const float*)d_in[20];
    const float* fw  = (const float*)d_in[21]; const float* fb  = (const float*)d_in[22];
    float* out = (float*)d_out;

    const int B = in_sizes[0] / (224 * 224);

    float* arena = nullptr;
    cudaGetSymbolAddress((void**)&arena, g_arena);
    float* D7  = arena + OFF_D7;
    float* D14 = arena + OFF_D14;
    float* D28 = arena + OFF_D28;
    float* C1b = arena + OFF_C1;
    float* SK1 = arena + OFF_SK1;
    float* C2b = arena + OFF_C2;
    float* SK2 = arena + OFF_SK2;
    float* C3b = arena + OFF_C3;
    float* C4b = arena + OFF_C4;
    float* ST  = arena + OFF_STATS;
    float* ST1 = ST;        // B*8*2
    float* ST2 = ST + 256;  // B*4*2
    float* ST3 = ST + 384;  // B*2*2
    float* ST4 = ST + 448;  // B*1*2

    // 1) fused SIFT (all scales) + stats zeroing
    {
        int nblk = B * 49 + (B * 196 + 7) / 8 + (B * 784 + 7) / 8;
        sift_all_kernel<<<nblk, 256>>>(x, D7, D14, D28, ST, B);
    }
    // 2) fused skip convs
    {
        int tot = B * (32 * 196 + 16 * 784);
        skip_both_kernel<<<(tot + 255) / 256, 256>>>(D14, D28, s1w, s1b, s2w, s2b, SK1, SK2, B);
    }
    // 3) convT1: 128->32, 7->14, stats out (G=8)
    {
        constexpr int SM = (128*9*9 + 2*128*16 + 448*8 + 4) * 4;
        auto k = convt_tile<128,128,32,2,7,7,7,8,false,true,1,8>;
        cudaFuncSetAttribute(k, cudaFuncAttributeMaxDynamicSharedMemorySize, SM);
        k<<<dim3(1,16,B), 448, SM>>>(D7, D7, d1w, d1b, nullptr, nullptr, nullptr, ST1, C1b);
    }
    // 4) convT2: cat(GN8(C1b), SK1) 64->16, 14->28, stats out (G=4)
    {
        constexpr int SM = (64*9*16 + 2*64*16 + 448*8 + 2*32 + 4) * 4;
        auto k = convt_tile<64,32,16,2,14,14,7,4,true,true,8,4>;
        cudaFuncSetAttribute(k, cudaFuncAttributeMaxDynamicSharedMemorySize, SM);
        k<<<dim3(2,8,B), 448, SM>>>(C1b, SK1, d2w, d2b, g1w, g1b, ST1, ST2, C2b);
    }
    // 5) convT3: cat(GN4(C2b), SK2) 32->8, 28->56, stats out (G=2)
    {
        constexpr int SM = (32*9*30 + 2*32*16 + 448*8 + 2*16 + 4) * 4;
        auto k = convt_tile<32,16,8,2,28,28,7,2,true,true,4,2>;
        cudaFuncSetAttribute(k, cudaFuncAttributeMaxDynamicSharedMemorySize, SM);
        k<<<dim3(4,4,B), 448, SM>>>(C2b, SK2, d3w, d3b, g2w, g2b, ST2, ST3, C3b);
    }
    // 6) convT4: GN2(C3b) 8->4, 56->112, stats out (G=1)
    {
        constexpr int SM = (8*9*58 + 1*8*16 + 448*8 + 2*8 + 2) * 4;
        auto k = convt_tile<8,8,4,1,56,56,7,2,true,true,2,1>;
        cudaFuncSetAttribute(k, cudaFuncAttributeMaxDynamicSharedMemorySize, SM);
        k<<<dim3(8,4,B), 448, SM>>>(C3b, C3b, d4w, d4b, g3w, g3b, ST3, ST4, C4b);
    }
    // 7) fused GN1 + convT5 + joint bilateral + tanh*scale
    {
        dim3 grid(14, 14, B);
        jbf_fused_kernel<<<grid, 256>>>(C4b, x, fw, fb, g4w, g4b, ST4, out);
    }
}